// round 6
// baseline (speedup 1.0000x reference)
#include <cuda_runtime.h>
#include <cstdint>

// LIF forward scan, 4 time steps. x/out: [4, N] fp32, N = 8,388,608.
// Forward value of the surrogate spike == hard threshold (mem > 0.5).
// HBM-bound streaming: 134 MiB read + 134 MiB write.
//
// R5 changes vs R4:
//  - 2x coarsening: each thread owns two adjacent float4 per step
//    (8 independent front-batched LDG.128 -> MLP_p1 = 8).
//  - Stores use default (evict-normal) policy; reads keep __ldcs
//    (evict-first) so streaming reads don't displace dirty write lines
//    in L2 -> cross-replay write coalescing in the timed loop.

static constexpr int STEP = 4;

__device__ __forceinline__ void lif_step(float4& mem, const float4 xin, float4& s) {
    mem.x = fmaf(mem.x, 0.25f, xin.x); mem.y = fmaf(mem.y, 0.25f, xin.y);
    mem.z = fmaf(mem.z, 0.25f, xin.z); mem.w = fmaf(mem.w, 0.25f, xin.w);
    s.x = mem.x > 0.5f ? 1.f : 0.f;  s.y = mem.y > 0.5f ? 1.f : 0.f;
    s.z = mem.z > 0.5f ? 1.f : 0.f;  s.w = mem.w > 0.5f ? 1.f : 0.f;
    mem.x = s.x > 0.f ? 0.f : mem.x; mem.y = s.y > 0.f ? 0.f : mem.y;
    mem.z = s.z > 0.f ? 0.f : mem.z; mem.w = s.w > 0.f ? 0.f : mem.w;
}

__global__ __launch_bounds__(256)
void lif_fwd_kernel(const float4* __restrict__ x, float4* __restrict__ out, int n4) {
    // Each thread handles float4 indices (2i, 2i+1) at all 4 time steps.
    int i = (blockIdx.x * blockDim.x + threadIdx.x) * 2;
    if (i >= n4) return;

    // Front-batch all 8 loads: 4 steps x 2 vectors, independent addresses.
    float4 xa[STEP], xb[STEP];
#pragma unroll
    for (int t = 0; t < STEP; t++) {
        size_t base = (size_t)t * n4 + i;
        xa[t] = __ldcs(&x[base]);
        xb[t] = __ldcs(&x[base + 1]);
    }

    float4 ma = make_float4(0.f, 0.f, 0.f, 0.f);
    float4 mb = make_float4(0.f, 0.f, 0.f, 0.f);

#pragma unroll
    for (int t = 0; t < STEP; t++) {
        float4 sa, sb;
        lif_step(ma, xa[t], sa);
        lif_step(mb, xb[t], sb);
        size_t base = (size_t)t * n4 + i;
        out[base]     = sa;   // evict-normal stores (see header comment)
        out[base + 1] = sb;
    }
}

extern "C" void kernel_launch(void* const* d_in, const int* in_sizes, int n_in,
                              void* d_out, int out_size) {
    const float* x = (const float*)d_in[0];
    float* out = (float*)d_out;

    int total = in_sizes[0];          // STEP * N
    int n = total / STEP;             // 8,388,608 elements per step
    int n4 = n / 4;                   // 2,097,152 float4 per step

    int threads = 256;
    int work_per_block = threads * 2; // 2 float4 per thread
    int blocks = (n4 + work_per_block - 1) / work_per_block;  // 4096
    lif_fwd_kernel<<<blocks, threads>>>((const float4*)x, (float4*)out, n4);
}

// round 7
// speedup vs baseline: 1.1603x; 1.1603x over previous
#include <cuda_runtime.h>
#include <cstdint>

// LIF forward scan, 4 time steps. x/out: [4, N] fp32, N = 8,388,608.
// Forward value of the surrogate spike == hard threshold (mem > 0.5).
// HBM-bound streaming: 134 MiB read + 134 MiB write -> floor ~34us.
//
// R6: revert R5 coarsening (cost occupancy: 40 regs -> 6 CTAs/SM) and
// evict-normal stores (polluted L2 with zero reuse). Back to R4's
// 1-float4/thread + __ldcs/__stcs at 30 regs / full occupancy, with
// 512-thread blocks (fewer CTA launch/drain events, same occupancy).

static constexpr int STEP = 4;

__device__ __forceinline__ void lif_step(float4& mem, const float4 xin, float4& s) {
    mem.x = fmaf(mem.x, 0.25f, xin.x); mem.y = fmaf(mem.y, 0.25f, xin.y);
    mem.z = fmaf(mem.z, 0.25f, xin.z); mem.w = fmaf(mem.w, 0.25f, xin.w);
    s.x = mem.x > 0.5f ? 1.f : 0.f;  s.y = mem.y > 0.5f ? 1.f : 0.f;
    s.z = mem.z > 0.5f ? 1.f : 0.f;  s.w = mem.w > 0.5f ? 1.f : 0.f;
    mem.x = s.x > 0.f ? 0.f : mem.x; mem.y = s.y > 0.f ? 0.f : mem.y;
    mem.z = s.z > 0.f ? 0.f : mem.z; mem.w = s.w > 0.f ? 0.f : mem.w;
}

__global__ __launch_bounds__(512)
void lif_fwd_kernel(const float4* __restrict__ x, float4* __restrict__ out, int n4) {
    int i = blockIdx.x * blockDim.x + threadIdx.x;
    if (i >= n4) return;

    // 4 independent front-batched LDG.128 (one per time step), evict-first.
    float4 x0 = __ldcs(&x[0 * (size_t)n4 + i]);
    float4 x1 = __ldcs(&x[1 * (size_t)n4 + i]);
    float4 x2 = __ldcs(&x[2 * (size_t)n4 + i]);
    float4 x3 = __ldcs(&x[3 * (size_t)n4 + i]);

    float4 mem = make_float4(0.f, 0.f, 0.f, 0.f);
    float4 s;

    lif_step(mem, x0, s);
    __stcs(&out[0 * (size_t)n4 + i], s);

    lif_step(mem, x1, s);
    __stcs(&out[1 * (size_t)n4 + i], s);

    lif_step(mem, x2, s);
    __stcs(&out[2 * (size_t)n4 + i], s);

    lif_step(mem, x3, s);
    __stcs(&out[3 * (size_t)n4 + i], s);
}

extern "C" void kernel_launch(void* const* d_in, const int* in_sizes, int n_in,
                              void* d_out, int out_size) {
    const float* x = (const float*)d_in[0];
    float* out = (float*)d_out;

    int total = in_sizes[0];          // STEP * N
    int n = total / STEP;             // 8,388,608 elements per step
    int n4 = n / 4;                   // 2,097,152 float4 per step

    int threads = 512;
    int blocks = (n4 + threads - 1) / threads;  // 4096
    lif_fwd_kernel<<<blocks, threads>>>((const float4*)x, (float4*)out, n4);
}